// round 1
// baseline (speedup 1.0000x reference)
#include <cuda_runtime.h>

// Problem constants (fixed by setup_inputs)
#define N_PTS 262144
#define D     128
#define D4    32          // D / 4 (float4 per row)
#define K     512
#define NITER 5

// Tiling for the assignment (E-step) kernel
#define BP 128            // points per block
#define BC 64             // centroid chunk per smem stage
#define SE_STRIDE 32      // float4 stride for emb tile (broadcast reads -> no pad needed)
#define SC_STRIDE 33      // float4 stride for cent tile (pad to kill bank conflicts)
#define SMEM_F4   (BP * SE_STRIDE + BC * SC_STRIDE)   // 4096 + 2112 = 6208 float4
#define SMEM_BYTES (SMEM_F4 * 16)                      // 99328 B

// Scratch state (no device allocation allowed -> __device__ globals)
__device__ float g_cent[K * D];
__device__ float g_sums[K * D];
__device__ float g_counts[K];
__device__ int   g_assign[N_PTS];

// ---------------------------------------------------------------------------
// Init: copy init centroids into working buffer, zero accumulators
// ---------------------------------------------------------------------------
__global__ void init_kernel(const float* __restrict__ initc) {
    int i = blockIdx.x * blockDim.x + threadIdx.x;
    if (i < K * D) {
        g_cent[i] = initc[i];
        g_sums[i] = 0.0f;
    }
    if (i < K) g_counts[i] = 0.0f;
}

// ---------------------------------------------------------------------------
// E-step: dots = E @ C^T with fused argmax.
// Block: 256 threads as 16(tx) x 16(ty). Each thread: 8 points x 4 cents.
// Points for thread:   p = p0 + ty + 16*i   (i < 8)
// Cents per chunk:     c = ch*BC + tx + 16*j (j < 4)
// Argmax combined across tx lanes via shfl_xor (16-lane groups).
// ---------------------------------------------------------------------------
__global__ __launch_bounds__(256, 2) void assign_kernel(const float4* __restrict__ emb) {
    extern __shared__ float4 sm[];
    float4* sE = sm;                       // [BP][SE_STRIDE]
    float4* sC = sm + BP * SE_STRIDE;      // [BC][SC_STRIDE]

    const int t  = threadIdx.x;
    const int tx = t & 15;
    const int ty = t >> 4;
    const int p0 = blockIdx.x * BP;
    const float4* cent4 = (const float4*)g_cent;

    // Load embedding tile: 128 rows x 32 float4 (coalesced, conflict-free STS)
#pragma unroll
    for (int it = 0; it < 16; it++) {
        int f = t + it * 256;
        int r = f >> 5, c = f & 31;
        sE[r * SE_STRIDE + c] = emb[(size_t)(p0 + r) * D4 + c];
    }

    float best[8];
    int   bidx[8];
#pragma unroll
    for (int i = 0; i < 8; i++) { best[i] = -3.402823466e38f; bidx[i] = 0; }

    for (int ch = 0; ch < K / BC; ch++) {
        __syncthreads();
        // Load centroid chunk: 64 rows x 32 float4
#pragma unroll
        for (int it = 0; it < 8; it++) {
            int f = t + it * 256;
            int r = f >> 5, c = f & 31;
            sC[r * SC_STRIDE + c] = cent4[(size_t)(ch * BC + r) * D4 + c];
        }
        __syncthreads();

        float acc[8][4];
#pragma unroll
        for (int i = 0; i < 8; i++)
#pragma unroll
            for (int j = 0; j < 4; j++) acc[i][j] = 0.0f;

#pragma unroll 4
        for (int d4 = 0; d4 < D4; d4++) {
            float4 c4[4];
#pragma unroll
            for (int j = 0; j < 4; j++)
                c4[j] = sC[(tx + 16 * j) * SC_STRIDE + d4];
#pragma unroll
            for (int i = 0; i < 8; i++) {
                float4 e = sE[(ty + 16 * i) * SE_STRIDE + d4];
#pragma unroll
                for (int j = 0; j < 4; j++) {
                    acc[i][j] += e.x * c4[j].x;
                    acc[i][j] += e.y * c4[j].y;
                    acc[i][j] += e.z * c4[j].z;
                    acc[i][j] += e.w * c4[j].w;
                }
            }
        }

        // Update running argmax (first-max tie-break: lower index wins)
#pragma unroll
        for (int j = 0; j < 4; j++) {
            int idx = ch * BC + tx + 16 * j;
#pragma unroll
            for (int i = 0; i < 8; i++) {
                float v = acc[i][j];
                if (v > best[i] || (v == best[i] && idx < bidx[i])) {
                    best[i] = v; bidx[i] = idx;
                }
            }
        }
    }

    // Combine over the 16 tx lanes (stays within each 16-lane half-warp)
#pragma unroll
    for (int off = 1; off < 16; off <<= 1) {
#pragma unroll
        for (int i = 0; i < 8; i++) {
            float ov = __shfl_xor_sync(0xffffffffu, best[i], off);
            int   oi = __shfl_xor_sync(0xffffffffu, bidx[i], off);
            if (ov > best[i] || (ov == best[i] && oi < bidx[i])) {
                best[i] = ov; bidx[i] = oi;
            }
        }
    }

    if (tx == 0) {
#pragma unroll
        for (int i = 0; i < 8; i++)
            g_assign[p0 + ty + 16 * i] = bidx[i];
    }
}

// ---------------------------------------------------------------------------
// M-step accumulate: one warp per point; vectorized red.add (sm_90+)
// ---------------------------------------------------------------------------
__global__ void accum_kernel(const float4* __restrict__ emb) {
    int gw   = (blockIdx.x * blockDim.x + threadIdx.x) >> 5;
    int lane = threadIdx.x & 31;
    if (gw >= N_PTS) return;
    float4 v = emb[(size_t)gw * D4 + lane];
    int a = g_assign[gw];
    float* dst = g_sums + (size_t)a * D + lane * 4;
    asm volatile("red.global.add.v4.f32 [%0], {%1,%2,%3,%4};"
                 :: "l"(dst), "f"(v.x), "f"(v.y), "f"(v.z), "f"(v.w)
                 : "memory");
    if (lane == 0) atomicAdd(&g_counts[a], 1.0f);
}

// ---------------------------------------------------------------------------
// M-step finalize: mean (or keep old when empty), L2-normalize, zero scratch
// ---------------------------------------------------------------------------
__global__ void update_kernel() {
    int k = blockIdx.x;
    int d = threadIdx.x;   // 128 threads
    float cnt = g_counts[k];
    float s   = g_sums[(size_t)k * D + d];
    float old = g_cent[(size_t)k * D + d];
    float val = (cnt > 0.0f) ? (s / fmaxf(cnt, 1.0f)) : old;

    float sq = val * val;
#pragma unroll
    for (int off = 16; off > 0; off >>= 1)
        sq += __shfl_xor_sync(0xffffffffu, sq, off);

    __shared__ float wsum[4];
    int warp = d >> 5, lane = d & 31;
    if (lane == 0) wsum[warp] = sq;
    __syncthreads();
    float tot = wsum[0] + wsum[1] + wsum[2] + wsum[3];
    float nrm = fmaxf(sqrtf(tot), 1e-12f);

    g_cent[(size_t)k * D + d] = val / nrm;
    g_sums[(size_t)k * D + d] = 0.0f;
    if (d == 0) g_counts[k] = 0.0f;
}

// ---------------------------------------------------------------------------
// Output writers (branch on out_size for layout robustness)
// ---------------------------------------------------------------------------
__global__ void out_concat_f32(float* __restrict__ out) {
    int i = blockIdx.x * blockDim.x + threadIdx.x;
    if (i < N_PTS) out[i] = (float)g_assign[i];
    if (i < K * D) out[N_PTS + i] = g_cent[i];
}

__global__ void out_assign_i32(int* __restrict__ out) {
    int i = blockIdx.x * blockDim.x + threadIdx.x;
    if (i < N_PTS) out[i] = g_assign[i];
}

__global__ void out_cent_f32(float* __restrict__ out) {
    int i = blockIdx.x * blockDim.x + threadIdx.x;
    if (i < K * D) out[i] = g_cent[i];
}

// ---------------------------------------------------------------------------
extern "C" void kernel_launch(void* const* d_in, const int* in_sizes, int n_in,
                              void* d_out, int out_size) {
    const float* emb   = (const float*)d_in[0];
    const float* initc = (const float*)d_in[1];
    // Defensive: identify by size in case of input reordering
    if (n_in >= 2 && in_sizes[0] == K * D && in_sizes[1] == N_PTS * D) {
        const float* tmp = emb; emb = initc; initc = tmp;
    }

    cudaFuncSetAttribute(assign_kernel,
                         cudaFuncAttributeMaxDynamicSharedMemorySize, SMEM_BYTES);

    init_kernel<<<(K * D + 255) / 256, 256>>>(initc);

    for (int it = 0; it < NITER; it++) {
        assign_kernel<<<N_PTS / BP, 256, SMEM_BYTES>>>((const float4*)emb);
        accum_kernel<<<(N_PTS * 32) / 256, 256>>>((const float4*)emb);
        update_kernel<<<K, D>>>();
    }

    if (out_size == N_PTS) {
        out_assign_i32<<<N_PTS / 256, 256>>>((int*)d_out);
    } else if (out_size == K * D) {
        out_cent_f32<<<(K * D) / 256, 256>>>((float*)d_out);
    } else {
        out_concat_f32<<<(N_PTS + 255) / 256, 256>>>((float*)d_out);
    }
}

// round 6
// speedup vs baseline: 1.6856x; 1.6856x over previous
#include <cuda_runtime.h>
#include <cuda_bf16.h>
#include <cstdint>

// Problem constants
#define N_PTS 262144
#define D     128
#define D4    32
#define K     512
#define NITER 5

// E-step tiling
#define BP        128      // points per CTA tile (M)
#define NCHUNK    64       // centroids per chunk (N per chunk)
#define NCHUNKS   8        // 512 / 64
#define KSUB      2        // K split into 2 subtiles of 64 bf16 (128B rows)

// SMEM layout
#define A_SPLIT_BYTES  32768          // 128 rows * 2 subs * 128B
#define A_TOTAL        (3 * A_SPLIT_BYTES)            // 98304
#define B_SPLIT_BYTES  16384          // 64 rows * 2 subs * 128B
#define B_SLOT_BYTES   (3 * B_SPLIT_BYTES)            // 49152
#define B_TOTAL        (2 * B_SLOT_BYTES)             // 98304
#define SMEM_DYN_BYTES (1024 + A_TOTAL + B_TOTAL)     // 197632

// bf16 MMA idesc: dtype=F32(1<<4), a=BF16(1<<7), b=BF16(1<<10), N=64(8<<17), M=128(8<<24)
#define MMA_IDESC 0x08100490u

// SW128 smem descriptor base: layout=SW128(2<<61), version=1(1<<46), SBO=64, LBO=1
#define SMEM_DESC_BASE 0x4000404000010000ULL
#define SW128(o) ((o) ^ ((((unsigned)(o)) >> 3) & 0x70u))

// Arch-feature gate: tcgen05 only legal in the sm_103a-specific pass.
#if defined(__CUDA_ARCH__) && (defined(__CUDA_ARCH_FEAT_SM103_ALL) || \
                               defined(__CUDA_ARCH_FEAT_SM100_ALL) || \
                               defined(__CUDA_ARCH_FEAT_SM101_ALL))
#define HAVE_TCGEN05 1
#else
#define HAVE_TCGEN05 0
#endif

// Scratch state
__device__ float g_cent[K * D];
__device__ float g_sums[K * D];
__device__ float g_counts[K];
__device__ int   g_assign[N_PTS];

// ---------------------------------------------------------------------------
// PTX helpers
// ---------------------------------------------------------------------------
__device__ __forceinline__ unsigned smem_u32(const void* p) {
    unsigned a;
    asm("{ .reg .u64 t; cvta.to.shared.u64 t, %1; cvt.u32.u64 %0, t; }"
        : "=r"(a) : "l"(p));
    return a;
}

#define STS32(addr, val) \
    asm volatile("st.shared.b32 [%0], %1;" :: "r"(addr), "r"(val) : "memory")

#define MBARRIER_INIT(a, c) \
    asm volatile("mbarrier.init.shared.b64 [%0], %1;" :: "r"(a), "r"(c) : "memory")

#define MBARRIER_INVAL(a) \
    asm volatile("mbarrier.inval.shared.b64 [%0];" :: "r"(a) : "memory")

#define MBARRIER_WAIT_PARITY(mbar, parity) do { \
    unsigned _m = (mbar), _p = (parity), _d; \
    asm volatile("{\n\t.reg .pred p;\n\t" \
        "mbarrier.try_wait.parity.acquire.cta.shared::cta.b64 p, [%1], %2;\n\t" \
        "selp.b32 %0, 1, 0, p;\n\t}" : "=r"(_d) : "r"(_m), "r"(_p) : "memory"); \
    if (!_d) { \
        asm volatile("{\n\t.reg .pred P1;\n\t" \
            "WL_%=:\n\t" \
            "mbarrier.try_wait.parity.acquire.cta.shared::cta.b64 P1, [%0], %1, 0x989680;\n\t" \
            "@P1 bra.uni WD_%=;\n\tbra.uni WL_%=;\n\tWD_%=:\n\t}" \
            :: "r"(_m), "r"(_p) : "memory"); \
    } \
} while (0)

#if HAVE_TCGEN05
#define TCGEN05_ALLOC(sa, n) \
    asm volatile("tcgen05.alloc.cta_group::1.sync.aligned.shared::cta.b32 [%0], %1;" \
                 :: "r"(sa), "r"(n) : "memory")
#define TCGEN05_DEALLOC(t, n) \
    asm volatile("tcgen05.dealloc.cta_group::1.sync.aligned.b32 %0, %1;" :: "r"(t), "r"(n))
#define TCGEN05_RELINQUISH() \
    asm volatile("tcgen05.relinquish_alloc_permit.cta_group::1.sync.aligned;")
#define TCGEN05_COMMIT(m) \
    asm volatile("tcgen05.commit.cta_group::1.mbarrier::arrive::one.shared::cluster.b64 [%0];" \
                 :: "r"(m) : "memory")
#define TCGEN05_FENCE_BEFORE() asm volatile("tcgen05.fence::before_thread_sync;" ::: "memory")
#define TCGEN05_FENCE_AFTER()  asm volatile("tcgen05.fence::after_thread_sync;"  ::: "memory")
#define TCGEN05_WAIT_LD()      asm volatile("tcgen05.wait::ld.sync.aligned;" ::: "memory")
#define FENCE_PROXY_ASYNC()    asm volatile("fence.proxy.async.shared::cta;" ::: "memory")

#define TCGEN05_LD_32X32B_X32(r, tmem_addr) \
    asm volatile( \
        "tcgen05.ld.sync.aligned.32x32b.x32.b32 " \
        "{%0, %1, %2, %3, %4, %5, %6, %7, " \
        " %8, %9, %10, %11, %12, %13, %14, %15, " \
        " %16, %17, %18, %19, %20, %21, %22, %23, " \
        " %24, %25, %26, %27, %28, %29, %30, %31}, [%32];" \
        : "=r"((r)[0]),  "=r"((r)[1]),  "=r"((r)[2]),  "=r"((r)[3]), \
          "=r"((r)[4]),  "=r"((r)[5]),  "=r"((r)[6]),  "=r"((r)[7]), \
          "=r"((r)[8]),  "=r"((r)[9]),  "=r"((r)[10]), "=r"((r)[11]), \
          "=r"((r)[12]), "=r"((r)[13]), "=r"((r)[14]), "=r"((r)[15]), \
          "=r"((r)[16]), "=r"((r)[17]), "=r"((r)[18]), "=r"((r)[19]), \
          "=r"((r)[20]), "=r"((r)[21]), "=r"((r)[22]), "=r"((r)[23]), \
          "=r"((r)[24]), "=r"((r)[25]), "=r"((r)[26]), "=r"((r)[27]), \
          "=r"((r)[28]), "=r"((r)[29]), "=r"((r)[30]), "=r"((r)[31]) \
        : "r"(tmem_addr))

__device__ __forceinline__ void mma_bf16_ss(unsigned d_tmem, unsigned long long a_desc,
                                            unsigned long long b_desc, unsigned en) {
    asm volatile(
        "{\n\t.reg .pred p;\n\tsetp.ne.u32 p, %4, 0;\n\t"
        "tcgen05.mma.cta_group::1.kind::f16 [%0], %1, %2, %3, {%5, %5, %5, %5}, p;\n\t}"
        :: "r"(d_tmem), "l"(a_desc), "l"(b_desc), "r"(MMA_IDESC), "r"(en), "r"(0u)
        : "memory");
}
#endif  // HAVE_TCGEN05

__device__ __forceinline__ unsigned long long mk_desc(unsigned byte_addr) {
    return SMEM_DESC_BASE | (unsigned long long)((byte_addr >> 4) & 0x3FFFu);
}

// fp32 -> 3x bf16 split (a = ah + al + ar), packed pairs
__device__ __forceinline__ void split3_pack(float x, float y,
                                            unsigned& ph, unsigned& pl, unsigned& pr) {
    __nv_bfloat16 xh = __float2bfloat16_rn(x);
    float xr1 = x - __bfloat162float(xh);
    __nv_bfloat16 xl = __float2bfloat16_rn(xr1);
    __nv_bfloat16 xr = __float2bfloat16_rn(xr1 - __bfloat162float(xl));
    __nv_bfloat16 yh = __float2bfloat16_rn(y);
    float yr1 = y - __bfloat162float(yh);
    __nv_bfloat16 yl = __float2bfloat16_rn(yr1);
    __nv_bfloat16 yr = __float2bfloat16_rn(yr1 - __bfloat162float(yl));
    ph = (unsigned)__bfloat16_as_ushort(xh) | ((unsigned)__bfloat16_as_ushort(yh) << 16);
    pl = (unsigned)__bfloat16_as_ushort(xl) | ((unsigned)__bfloat16_as_ushort(yl) << 16);
    pr = (unsigned)__bfloat16_as_ushort(xr) | ((unsigned)__bfloat16_as_ushort(yr) << 16);
}

// ---------------------------------------------------------------------------
__global__ void init_kernel(const float* __restrict__ initc) {
    int i = blockIdx.x * blockDim.x + threadIdx.x;
    if (i < K * D) { g_cent[i] = initc[i]; g_sums[i] = 0.0f; }
    if (i < K)     g_counts[i] = 0.0f;
}

// ---------------------------------------------------------------------------
// E-step, sm_103a: UNIFORM-warp tcgen05 pipeline, TWO commit mbarriers.
// 128 threads in lockstep phases separated by __syncthreads:
//   loop c: load+split B(c+1) -> sync -> tid0 issues MMA(c+1) -> commit to
//           mbar[(c+1)&1] -> all wait mbar[c&1] parity (c>>1)&1 -> LDTM(c).
// Two barriers => <=1 outstanding commit per barrier => no parity aliasing
// (round-5 deadlock). Split accumulators: TMEM slot (c&3)*128, hh +0, small +64.
// ---------------------------------------------------------------------------
__global__ void __launch_bounds__(128, 1)
assign_tc_kernel(const float4* __restrict__ emb) {
#if HAVE_TCGEN05
    extern __shared__ char smem[];
    const unsigned smem_base = smem_u32(smem);
    const unsigned tiles = (smem_base + 1024u + 1023u) & ~1023u;
    const unsigned a_base = tiles;                 // 3 splits x 32KB
    const unsigned b_base = tiles + A_TOTAL;       // 2 slots  x 48KB

    const int tid = threadIdx.x;
    const int wid = tid >> 5;
    const int p0  = blockIdx.x * BP;
    const float4* cent4 = (const float4*)g_cent;

    if (tid == 0) {
        MBARRIER_INIT(smem_base + 8, 1);
        MBARRIER_INIT(smem_base + 16, 1);
    }
    if (wid == 0) TCGEN05_ALLOC(smem_base, 512);

    // ---- Prologue: load + split A (thread t -> row t, 32 float4) ----
    {
        const float4* src = emb + (size_t)(p0 + tid) * D4;
#pragma unroll
        for (int q = 0; q < 32; q++) {
            float4 v = src[q];
            unsigned sub = (unsigned)(q >> 4);
            unsigned off = (unsigned)(tid * 128 + 8 * (q & 15));
            unsigned base = a_base + sub * 16384u;
            unsigned ph, pl, pr;
            split3_pack(v.x, v.y, ph, pl, pr);
            unsigned sw0 = SW128(off);
            STS32(base + sw0, ph);
            STS32(base + A_SPLIT_BYTES + sw0, pl);
            STS32(base + 2 * A_SPLIT_BYTES + sw0, pr);
            split3_pack(v.z, v.w, ph, pl, pr);
            unsigned sw1 = SW128(off + 4);
            STS32(base + sw1, ph);
            STS32(base + A_SPLIT_BYTES + sw1, pl);
            STS32(base + 2 * A_SPLIT_BYTES + sw1, pr);
        }
    }
    __syncthreads();
    unsigned tmem_base;
    asm volatile("ld.shared.b32 %0, [%1];" : "=r"(tmem_base) : "r"(smem_base));

    // B chunk loader (all 128 threads)
    auto loadB = [&](int c) {
        const unsigned sbase = b_base + (unsigned)((c & 1) * B_SLOT_BYTES);
#pragma unroll
        for (int it = 0; it < 16; it++) {           // 2048 float4 / 128 threads
            int idx = tid + it * 128;
            int r = idx >> 5, q = idx & 31;
            float4 v = cent4[(size_t)(c * NCHUNK + r) * D4 + q];
            unsigned sub = (unsigned)(q >> 4);
            unsigned off = (unsigned)(r * 128 + 8 * (q & 15));
            unsigned base = sbase + sub * 8192u;
            unsigned ph, pl, pr;
            split3_pack(v.x, v.y, ph, pl, pr);
            unsigned sw0 = SW128(off);
            STS32(base + sw0, ph);
            STS32(base + B_SPLIT_BYTES + sw0, pl);
            STS32(base + 2 * B_SPLIT_BYTES + sw0, pr);
            split3_pack(v.z, v.w, ph, pl, pr);
            unsigned sw1 = SW128(off + 4);
            STS32(base + sw1, ph);
            STS32(base + B_SPLIT_BYTES + sw1, pl);
            STS32(base + 2 * B_SPLIT_BYTES + sw1, pr);
        }
    };

    // MMA issue for one chunk (tid 0). hh -> slot+0, small -> slot+64.
    // Commits to mbar[c&1].
    auto issue_chunk = [&](int c) {
        const int PA[6] = {0, 0, 1, 1, 0, 2};
        const int PB[6] = {0, 1, 0, 1, 2, 0};
        const unsigned d_hh = tmem_base + (unsigned)(128 * (c & 3));
        const unsigned d_sm = d_hh + 64;
        const unsigned bslot = b_base + (unsigned)((c & 1) * B_SLOT_BYTES);
        unsigned en_hh = 0, en_sm = 0;
#pragma unroll
        for (int sub = 0; sub < KSUB; sub++) {
#pragma unroll
            for (int ks = 0; ks < 4; ks++) {
                const unsigned ko  = (unsigned)(sub * 16384 + ks * 32);
                const unsigned kob = (unsigned)(sub * 8192 + ks * 32);
                mma_bf16_ss(d_hh, mk_desc(a_base + ko),
                            mk_desc(bslot + kob), en_hh);
                en_hh = 1;
#pragma unroll
                for (int p = 1; p < 6; p++) {
                    mma_bf16_ss(d_sm,
                                mk_desc(a_base + PA[p] * A_SPLIT_BYTES + ko),
                                mk_desc(bslot + PB[p] * B_SPLIT_BYTES + kob),
                                en_sm);
                    en_sm = 1;
                }
            }
        }
        TCGEN05_COMMIT(smem_base + 8u + 8u * (unsigned)(c & 1));
    };

    // ---- Pipeline ----
    loadB(0);
    __syncthreads();
    if (tid == 0) { FENCE_PROXY_ASYNC(); TCGEN05_FENCE_AFTER(); issue_chunk(0); }

    float best = -3.402823466e38f;
    int   bidx = 0;
    unsigned rh[32], rs[32];

    for (int c = 0; c < NCHUNKS; c++) {
        if (c < NCHUNKS - 1) loadB(c + 1);
        __syncthreads();    // B(c+1) visible to all; orders prior LDTM fences
        if (c < NCHUNKS - 1 && tid == 0) {
            FENCE_PROXY_ASYNC(); TCGEN05_FENCE_AFTER(); issue_chunk(c + 1);
        }

        // Wait chunk c: barrier (c&1), parity (c>>1)&1. <=1 outstanding commit
        // per barrier -> no parity aliasing.
        MBARRIER_WAIT_PARITY(smem_base + 8u + 8u * (unsigned)(c & 1), (c >> 1) & 1);
        TCGEN05_FENCE_AFTER();
        const unsigned d_hh = tmem_base + (unsigned)(128 * (c & 3));
        const unsigned d_sm = d_hh + 64;
#pragma unroll
        for (int half = 0; half < 2; half++) {
            TCGEN05_LD_32X32B_X32(rh, d_hh + 32u * half);
            TCGEN05_LD_32X32B_X32(rs, d_sm + 32u * half);
            TCGEN05_WAIT_LD();
#pragma unroll
            for (int j = 0; j < 32; j++) {
                float v = __uint_as_float(rh[j]) + __uint_as_float(rs[j]);
                int idx = 64 * c + 32 * half + j;
                if (v > best) { best = v; bidx = idx; }
            }
        }
        TCGEN05_FENCE_BEFORE();
    }

    g_assign[p0 + tid] = bidx;   // row = tid

    __syncthreads();
    if (tid == 0) {
        MBARRIER_INVAL(smem_base + 8);
        MBARRIER_INVAL(smem_base + 16);
    }
    __syncthreads();
    if (wid == 0) {
        TCGEN05_RELINQUISH();
        TCGEN05_DEALLOC(tmem_base, 512);
    }
#else
    // ---------------- SIMT fp32 fallback (non-'a' compile pass) ----------------
    extern __shared__ char smem_raw[];
    float4* sE = (float4*)smem_raw;              // [BP][32]
    float4* sC = sE + BP * 32;                   // [64][33] padded

    const int t   = threadIdx.x;                 // 128 threads
    const int tx  = t & 15;
    const int ty8 = t >> 4;                      // 0..7
    const int p0  = blockIdx.x * BP;
    const float4* cent4 = (const float4*)g_cent;

    for (int it = 0; it < 32; it++) {
        int f = t + it * 128;
        int r = f >> 5, c = f & 31;
        sE[r * 32 + c] = emb[(size_t)(p0 + r) * D4 + c];
    }

    float best[16];
    int   bidx[16];
#pragma unroll
    for (int i = 0; i < 16; i++) { best[i] = -3.402823466e38f; bidx[i] = 0; }

    for (int ch = 0; ch < K / 64; ch++) {
        __syncthreads();
        for (int it = 0; it < 16; it++) {
            int f = t + it * 128;
            int r = f >> 5, c = f & 31;
            sC[r * 33 + c] = cent4[(size_t)(ch * 64 + r) * D4 + c];
        }
        __syncthreads();

        float acc[16][4];
#pragma unroll
        for (int i = 0; i < 16; i++)
#pragma unroll
            for (int j = 0; j < 4; j++) acc[i][j] = 0.0f;

#pragma unroll 2
        for (int d4 = 0; d4 < D4; d4++) {
            float4 c4[4];
#pragma unroll
            for (int j = 0; j < 4; j++) c4[j] = sC[(tx + 16 * j) * 33 + d4];
#pragma unroll
            for (int i = 0; i < 16; i++) {
                float4 e = sE[(ty8 + 8 * i) * 32 + d4];
#pragma unroll
                for (int j = 0; j < 4; j++) {
                    acc[i][j] += e.x * c4[j].x;
                    acc[i][j] += e.y * c4[j].y;
                    acc[i][j] += e.z * c4[j].z;
                    acc[i][j] += e.w * c4[j].w;
                }
            }
        }
#pragma unroll
        for (int j = 0; j < 4; j++) {
            int idx = ch * 64 + tx + 16 * j;
#pragma unroll
            for (int i = 0; i < 16; i++) {
                float v = acc[i][j];
                if (v > best[i] || (v == best[i] && idx < bidx[i])) {
                    best[i] = v; bidx[i] = idx;
                }
            }
        }
    }

#pragma unroll
    for (int off = 1; off < 16; off <<= 1) {
#pragma unroll
        for (int i = 0; i < 16; i++) {
            float ov = __shfl_xor_sync(0xffffffffu, best[i], off);
            int   oi = __shfl_xor_sync(0xffffffffu, bidx[i], off);
            if (ov > best[i] || (ov == best[i] && oi < bidx[i])) {
                best[i] = ov; bidx[i] = oi;
            }
        }
    }
    if (tx == 0) {
#pragma unroll
        for (int i = 0; i < 16; i++)
            g_assign[p0 + ty8 + 8 * i] = bidx[i];
    }
#endif
}

// ---------------------------------------------------------------------------
__global__ void accum_kernel(const float4* __restrict__ emb) {
    int gw   = (blockIdx.x * blockDim.x + threadIdx.x) >> 5;
    int lane = threadIdx.x & 31;
    if (gw >= N_PTS) return;
    float4 v = emb[(size_t)gw * D4 + lane];
    int a = g_assign[gw];
    float* dst = g_sums + (size_t)a * D + lane * 4;
    asm volatile("red.global.add.v4.f32 [%0], {%1,%2,%3,%4};"
                 :: "l"(dst), "f"(v.x), "f"(v.y), "f"(v.z), "f"(v.w)
                 : "memory");
    if (lane == 0) atomicAdd(&g_counts[a], 1.0f);
}

// ---------------------------------------------------------------------------
__global__ void update_kernel() {
    int k = blockIdx.x;
    int d = threadIdx.x;
    float cnt = g_counts[k];
    float s   = g_sums[(size_t)k * D + d];
    float old = g_cent[(size_t)k * D + d];
    float val = (cnt > 0.0f) ? (s / fmaxf(cnt, 1.0f)) : old;

    float sq = val * val;
#pragma unroll
    for (int off = 16; off > 0; off >>= 1)
        sq += __shfl_xor_sync(0xffffffffu, sq, off);

    __shared__ float wsum[4];
    int warp = d >> 5, lane = d & 31;
    if (lane == 0) wsum[warp] = sq;
    __syncthreads();
    float tot = wsum[0] + wsum[1] + wsum[2] + wsum[3];
    float nrm = fmaxf(sqrtf(tot), 1e-12f);

    g_cent[(size_t)k * D + d] = val / nrm;
    g_sums[(size_t)k * D + d] = 0.0f;
    if (d == 0) g_counts[k] = 0.0f;
}

// ---------------------------------------------------------------------------
__global__ void out_concat_f32(float* __restrict__ out) {
    int i = blockIdx.x * blockDim.x + threadIdx.x;
    if (i < N_PTS) out[i] = (float)g_assign[i];
    if (i < K * D) out[N_PTS + i] = g_cent[i];
}
__global__ void out_assign_i32(int* __restrict__ out) {
    int i = blockIdx.x * blockDim.x + threadIdx.x;
    if (i < N_PTS) out[i] = g_assign[i];
}
__global__ void out_cent_f32(float* __restrict__ out) {
    int i = blockIdx.x * blockDim.x + threadIdx.x;
    if (i < K * D) out[i] = g_cent[i];
}

// ---------------------------------------------------------------------------
extern "C" void kernel_launch(void* const* d_in, const int* in_sizes, int n_in,
                              void* d_out, int out_size) {
    const float* emb   = (const float*)d_in[0];
    const float* initc = (const float*)d_in[1];
    if (n_in >= 2 && in_sizes[0] == K * D && in_sizes[1] == N_PTS * D) {
        const float* tmp = emb; emb = initc; initc = tmp;
    }

    cudaFuncSetAttribute(assign_tc_kernel,
                         cudaFuncAttributeMaxDynamicSharedMemorySize, SMEM_DYN_BYTES);

    init_kernel<<<(K * D + 255) / 256, 256>>>(initc);

    for (int it = 0; it < NITER; it++) {
        assign_tc_kernel<<<N_PTS / BP, 128, SMEM_DYN_BYTES>>>((const float4*)emb);
        accum_kernel<<<(N_PTS * 32) / 256, 256>>>((const float4*)emb);
        update_kernel<<<K, D>>>();
    }

    if (out_size == N_PTS) {
        out_assign_i32<<<N_PTS / 256, 256>>>((int*)d_out);
    } else if (out_size == K * D) {
        out_cent_f32<<<(K * D) / 256, 256>>>((float*)d_out);
    } else {
        out_concat_f32<<<(N_PTS + 255) / 256, 256>>>((float*)d_out);
    }
}

// round 7
// speedup vs baseline: 2.0664x; 1.2259x over previous
#include <cuda_runtime.h>
#include <cuda_bf16.h>
#include <cstdint>

// Problem constants
#define N_PTS 262144
#define D     128
#define D4    32
#define K     512
#define NITER 5
#define NTILE (N_PTS / 128)    // 2048 point tiles

// E-step tiling
#define BP        128
#define NCHUNK    64
#define NCHUNKS   8
#define KSUB      2

// SMEM layout (same as round 6)
#define A_SPLIT_BYTES  32768
#define A_TOTAL        (3 * A_SPLIT_BYTES)            // 98304
#define B_SPLIT_BYTES  16384
#define B_SLOT_BYTES   (3 * B_SPLIT_BYTES)            // 49152
#define B_TOTAL        (2 * B_SLOT_BYTES)             // 98304
#define SMEM_DYN_BYTES (1024 + A_TOTAL + B_TOTAL)     // 197632

// Per-tile prepacked A image: [3 splits][2 subs][128 rows][128B] = 98304 B = 24576 u32
#define A_TILE_U32  24576
// Prepacked B image: [3 splits][2 subs][512 rows][128B] = 393216 B = 98304 u32
#define B_IMG_U32   98304

// bf16 MMA idesc: dtype=F32, a=BF16, b=BF16, N=64, M=128
#define MMA_IDESC 0x08100490u
#define SMEM_DESC_BASE 0x4000404000010000ULL
#define SW128(o) ((o) ^ ((((unsigned)(o)) >> 3) & 0x70u))

#if defined(__CUDA_ARCH__) && (defined(__CUDA_ARCH_FEAT_SM103_ALL) || \
                               defined(__CUDA_ARCH_FEAT_SM100_ALL) || \
                               defined(__CUDA_ARCH_FEAT_SM101_ALL))
#define HAVE_TCGEN05 1
#else
#define HAVE_TCGEN05 0
#endif

// Scratch state (no device allocation allowed)
__device__ float    g_cent[K * D];
__device__ float    g_sums[K * D];
__device__ float    g_counts[K];
__device__ int      g_assign[N_PTS];
__device__ unsigned g_embA[NTILE * A_TILE_U32];   // 192 MB prepacked A splits
__device__ unsigned g_centB[B_IMG_U32];           // 384 KB prepacked B splits

// ---------------------------------------------------------------------------
// PTX helpers
// ---------------------------------------------------------------------------
__device__ __forceinline__ unsigned smem_u32(const void* p) {
    unsigned a;
    asm("{ .reg .u64 t; cvta.to.shared.u64 t, %1; cvt.u32.u64 %0, t; }"
        : "=r"(a) : "l"(p));
    return a;
}

#define MBARRIER_INIT(a, c) \
    asm volatile("mbarrier.init.shared.b64 [%0], %1;" :: "r"(a), "r"(c) : "memory")
#define MBARRIER_INVAL(a) \
    asm volatile("mbarrier.inval.shared.b64 [%0];" :: "r"(a) : "memory")
#define MBARRIER_EXPECT_TX(a, b) \
    asm volatile("mbarrier.arrive.expect_tx.shared.b64 _, [%0], %1;" \
                 :: "r"(a), "r"(b) : "memory")

#define MBARRIER_WAIT_PARITY(mbar, parity) do { \
    unsigned _m = (mbar), _p = (parity), _d; \
    asm volatile("{\n\t.reg .pred p;\n\t" \
        "mbarrier.try_wait.parity.acquire.cta.shared::cta.b64 p, [%1], %2;\n\t" \
        "selp.b32 %0, 1, 0, p;\n\t}" : "=r"(_d) : "r"(_m), "r"(_p) : "memory"); \
    if (!_d) { \
        asm volatile("{\n\t.reg .pred P1;\n\t" \
            "WL_%=:\n\t" \
            "mbarrier.try_wait.parity.acquire.cta.shared::cta.b64 P1, [%0], %1, 0x989680;\n\t" \
            "@P1 bra.uni WD_%=;\n\tbra.uni WL_%=;\n\tWD_%=:\n\t}" \
            :: "r"(_m), "r"(_p) : "memory"); \
    } \
} while (0)

#define BULK_G2S(dst, src, bytes, mbar) \
    asm volatile("cp.async.bulk.shared::cta.global.mbarrier::complete_tx::bytes " \
                 "[%0], [%1], %2, [%3];" \
                 :: "r"(dst), "l"(src), "r"(bytes), "r"(mbar) : "memory")

#if HAVE_TCGEN05
#define TCGEN05_ALLOC(sa, n) \
    asm volatile("tcgen05.alloc.cta_group::1.sync.aligned.shared::cta.b32 [%0], %1;" \
                 :: "r"(sa), "r"(n) : "memory")
#define TCGEN05_DEALLOC(t, n) \
    asm volatile("tcgen05.dealloc.cta_group::1.sync.aligned.b32 %0, %1;" :: "r"(t), "r"(n))
#define TCGEN05_RELINQUISH() \
    asm volatile("tcgen05.relinquish_alloc_permit.cta_group::1.sync.aligned;")
#define TCGEN05_COMMIT(m) \
    asm volatile("tcgen05.commit.cta_group::1.mbarrier::arrive::one.shared::cluster.b64 [%0];" \
                 :: "r"(m) : "memory")
#define TCGEN05_FENCE_BEFORE() asm volatile("tcgen05.fence::before_thread_sync;" ::: "memory")
#define TCGEN05_FENCE_AFTER()  asm volatile("tcgen05.fence::after_thread_sync;"  ::: "memory")
#define TCGEN05_WAIT_LD()      asm volatile("tcgen05.wait::ld.sync.aligned;" ::: "memory")

#define TCGEN05_LD_32X32B_X32(r, tmem_addr) \
    asm volatile( \
        "tcgen05.ld.sync.aligned.32x32b.x32.b32 " \
        "{%0, %1, %2, %3, %4, %5, %6, %7, " \
        " %8, %9, %10, %11, %12, %13, %14, %15, " \
        " %16, %17, %18, %19, %20, %21, %22, %23, " \
        " %24, %25, %26, %27, %28, %29, %30, %31}, [%32];" \
        : "=r"((r)[0]),  "=r"((r)[1]),  "=r"((r)[2]),  "=r"((r)[3]), \
          "=r"((r)[4]),  "=r"((r)[5]),  "=r"((r)[6]),  "=r"((r)[7]), \
          "=r"((r)[8]),  "=r"((r)[9]),  "=r"((r)[10]), "=r"((r)[11]), \
          "=r"((r)[12]), "=r"((r)[13]), "=r"((r)[14]), "=r"((r)[15]), \
          "=r"((r)[16]), "=r"((r)[17]), "=r"((r)[18]), "=r"((r)[19]), \
          "=r"((r)[20]), "=r"((r)[21]), "=r"((r)[22]), "=r"((r)[23]), \
          "=r"((r)[24]), "=r"((r)[25]), "=r"((r)[26]), "=r"((r)[27]), \
          "=r"((r)[28]), "=r"((r)[29]), "=r"((r)[30]), "=r"((r)[31]) \
        : "r"(tmem_addr))

__device__ __forceinline__ void mma_bf16_ss(unsigned d_tmem, unsigned long long a_desc,
                                            unsigned long long b_desc, unsigned en) {
    asm volatile(
        "{\n\t.reg .pred p;\n\tsetp.ne.u32 p, %4, 0;\n\t"
        "tcgen05.mma.cta_group::1.kind::f16 [%0], %1, %2, %3, {%5, %5, %5, %5}, p;\n\t}"
        :: "r"(d_tmem), "l"(a_desc), "l"(b_desc), "r"(MMA_IDESC), "r"(en), "r"(0u)
        : "memory");
}
#endif  // HAVE_TCGEN05

__device__ __forceinline__ unsigned long long mk_desc(unsigned byte_addr) {
    return SMEM_DESC_BASE | (unsigned long long)((byte_addr >> 4) & 0x3FFFu);
}

// fp32 -> 3x bf16 split, packed pairs
__device__ __forceinline__ void split3_pack(float x, float y,
                                            unsigned& ph, unsigned& pl, unsigned& pr) {
    __nv_bfloat16 xh = __float2bfloat16_rn(x);
    float xr1 = x - __bfloat162float(xh);
    __nv_bfloat16 xl = __float2bfloat16_rn(xr1);
    __nv_bfloat16 xr = __float2bfloat16_rn(xr1 - __bfloat162float(xl));
    __nv_bfloat16 yh = __float2bfloat16_rn(y);
    float yr1 = y - __bfloat162float(yh);
    __nv_bfloat16 yl = __float2bfloat16_rn(yr1);
    __nv_bfloat16 yr = __float2bfloat16_rn(yr1 - __bfloat162float(yl));
    ph = (unsigned)__bfloat16_as_ushort(xh) | ((unsigned)__bfloat16_as_ushort(yh) << 16);
    pl = (unsigned)__bfloat16_as_ushort(xl) | ((unsigned)__bfloat16_as_ushort(yl) << 16);
    pr = (unsigned)__bfloat16_as_ushort(xr) | ((unsigned)__bfloat16_as_ushort(yr) << 16);
}

// ---------------------------------------------------------------------------
__global__ void init_kernel(const float* __restrict__ initc) {
    int i = blockIdx.x * blockDim.x + threadIdx.x;
    if (i < K * D) { g_cent[i] = initc[i]; g_sums[i] = 0.0f; }
    if (i < K)     g_counts[i] = 0.0f;
}

// ---------------------------------------------------------------------------
// Once per launch: pack embedding 3-way bf16 splits into swizzled tile images.
// Block = one 128-row tile, 8 warps; warp handles rows stride-8, lane = float4 col.
// ---------------------------------------------------------------------------
__global__ void emb_split_kernel(const float4* __restrict__ emb) {
    const int tile = blockIdx.x;
    const int w    = threadIdx.x >> 5;
    const int lane = threadIdx.x & 31;
    unsigned* out = g_embA + (size_t)tile * A_TILE_U32;
    const unsigned subbase = (unsigned)(lane >> 4) * 4096u;   // u32 units (16KB)
    for (int r = w; r < 128; r += 8) {
        float4 v = emb[(size_t)(tile * 128 + r) * D4 + lane];
        unsigned off = (unsigned)(r * 128 + 8 * (lane & 15));
        unsigned s0 = SW128(off) >> 2, s1 = SW128(off + 4) >> 2;
        unsigned ph, pl, pr, qh, ql, qr;
        split3_pack(v.x, v.y, ph, pl, pr);
        split3_pack(v.z, v.w, qh, ql, qr);
        out[subbase + s0]          = ph;  out[subbase + s1]          = qh;
        out[8192u + subbase + s0]  = pl;  out[8192u + subbase + s1]  = ql;
        out[16384u + subbase + s0] = pr;  out[16384u + subbase + s1] = qr;
    }
}

// ---------------------------------------------------------------------------
// Once per iteration: pack centroid splits into swizzled image
// [split][sub][512 rows][128B]. One warp per centroid row.
// ---------------------------------------------------------------------------
__global__ void cent_split_kernel() {
    const int gw   = (blockIdx.x * blockDim.x + threadIdx.x) >> 5;  // 0..511
    const int lane = threadIdx.x & 31;
    if (gw >= K) return;
    float4 v = ((const float4*)g_cent)[(size_t)gw * D4 + lane];
    const unsigned subbase = (unsigned)(lane >> 4) * 16384u;   // u32 units (64KB)
    unsigned off = (unsigned)(gw * 128 + 8 * (lane & 15));
    unsigned s0 = SW128(off) >> 2, s1 = SW128(off + 4) >> 2;
    unsigned ph, pl, pr, qh, ql, qr;
    split3_pack(v.x, v.y, ph, pl, pr);
    split3_pack(v.z, v.w, qh, ql, qr);
    g_centB[subbase + s0]           = ph;  g_centB[subbase + s1]           = qh;
    g_centB[32768u + subbase + s0]  = pl;  g_centB[32768u + subbase + s1]  = ql;
    g_centB[65536u + subbase + s0]  = pr;  g_centB[65536u + subbase + s1]  = qr;
}

// ---------------------------------------------------------------------------
// E-step, sm_103a: tcgen05 pipeline fed by cp.async.bulk from prepacked images.
// Sync skeleton identical to the passing round-6 design (two copy + two MMA
// mbarriers, <=1 outstanding commit per barrier; end-of-iter __syncthreads
// bounds warp skew to 1 iteration, protecting TMEM slot reuse distance 4 and
// B slot reuse distance 2).
// ---------------------------------------------------------------------------
__global__ void __launch_bounds__(128, 1)
assign_tc_kernel(const float4* __restrict__ emb) {
#if HAVE_TCGEN05
    extern __shared__ char smem[];
    const unsigned smem_base = smem_u32(smem);
    const unsigned tiles = (smem_base + 1024u + 1023u) & ~1023u;
    const unsigned a_base = tiles;
    const unsigned b_base = tiles + A_TOTAL;
    const unsigned mbA  = smem_base + 8;
    const unsigned mbCP = smem_base + 16;   // +16, +24
    const unsigned mbMM = smem_base + 32;   // +32, +40

    const int tid = threadIdx.x;
    const int wid = tid >> 5;

    if (tid == 0) {
        MBARRIER_INIT(mbA, 1);
        MBARRIER_INIT(mbCP, 1);     MBARRIER_INIT(mbCP + 8, 1);
        MBARRIER_INIT(mbMM, 1);     MBARRIER_INIT(mbMM + 8, 1);
    }
    if (wid == 0) TCGEN05_ALLOC(smem_base, 512);
    __syncthreads();
    unsigned tmem_base;
    asm volatile("ld.shared.b32 %0, [%1];" : "=r"(tmem_base) : "r"(smem_base));

    // Issue 6 bulk copies for one B chunk (8KB each: per split x sub)
    auto issue_copyB = [&](int c) {
        const unsigned mb = mbCP + 8u * (unsigned)(c & 1);
        const unsigned dslot = b_base + (unsigned)((c & 1) * B_SLOT_BYTES);
        MBARRIER_EXPECT_TX(mb, 49152u);
#pragma unroll
        for (int s = 0; s < 3; s++) {
#pragma unroll
            for (int h = 0; h < 2; h++) {
                const unsigned* src = g_centB + (size_t)s * 32768 + (size_t)h * 16384
                                      + (size_t)c * 2048;
                unsigned dst = dslot + (unsigned)(s * B_SPLIT_BYTES + h * 8192);
                BULK_G2S(dst, src, 8192u, mb);
            }
        }
    };

    // MMA issue for one chunk (tid 0). hh -> slot+0, small -> slot+64.
    auto issue_chunk = [&](int c) {
        const int PA[6] = {0, 0, 1, 1, 0, 2};
        const int PB[6] = {0, 1, 0, 1, 2, 0};
        const unsigned d_hh = tmem_base + (unsigned)(128 * (c & 3));
        const unsigned d_sm = d_hh + 64;
        const unsigned bslot = b_base + (unsigned)((c & 1) * B_SLOT_BYTES);
        unsigned en_hh = 0, en_sm = 0;
#pragma unroll
        for (int sub = 0; sub < KSUB; sub++) {
#pragma unroll
            for (int ks = 0; ks < 4; ks++) {
                const unsigned ko  = (unsigned)(sub * 16384 + ks * 32);
                const unsigned kob = (unsigned)(sub * 8192 + ks * 32);
                mma_bf16_ss(d_hh, mk_desc(a_base + ko),
                            mk_desc(bslot + kob), en_hh);
                en_hh = 1;
#pragma unroll
                for (int p = 1; p < 6; p++) {
                    mma_bf16_ss(d_sm,
                                mk_desc(a_base + PA[p] * A_SPLIT_BYTES + ko),
                                mk_desc(bslot + PB[p] * B_SPLIT_BYTES + kob),
                                en_sm);
                    en_sm = 1;
                }
            }
        }
        TCGEN05_COMMIT(mbMM + 8u * (unsigned)(c & 1));
    };

    // ---- Prologue: bulk-copy A tile + first B chunk, start MMA(0) ----
    if (tid == 0) {
        MBARRIER_EXPECT_TX(mbA, 98304u);
        BULK_G2S(a_base, g_embA + (size_t)blockIdx.x * A_TILE_U32, 98304u, mbA);
        issue_copyB(0);
        MBARRIER_WAIT_PARITY(mbA, 0);
        MBARRIER_WAIT_PARITY(mbCP, 0);
        issue_chunk(0);
    }

    float best = -3.402823466e38f;
    int   bidx = 0;
    unsigned rh[32], rs[32];

    for (int c = 0; c < NCHUNKS; c++) {
        if (tid == 0 && c < NCHUNKS - 1) {
            issue_copyB(c + 1);
            MBARRIER_WAIT_PARITY(mbCP + 8u * (unsigned)((c + 1) & 1),
                                 ((c + 1) >> 1) & 1);
            issue_chunk(c + 1);
        }

        MBARRIER_WAIT_PARITY(mbMM + 8u * (unsigned)(c & 1), (c >> 1) & 1);
        TCGEN05_FENCE_AFTER();
        const unsigned d_hh = tmem_base + (unsigned)(128 * (c & 3));
        const unsigned d_sm = d_hh + 64;
#pragma unroll
        for (int half = 0; half < 2; half++) {
            TCGEN05_LD_32X32B_X32(rh, d_hh + 32u * half);
            TCGEN05_LD_32X32B_X32(rs, d_sm + 32u * half);
            TCGEN05_WAIT_LD();
#pragma unroll
            for (int j = 0; j < 32; j++) {
                float v = __uint_as_float(rh[j]) + __uint_as_float(rs[j]);
                int idx = 64 * c + 32 * half + j;
                if (v > best) { best = v; bidx = idx; }
            }
        }
        TCGEN05_FENCE_BEFORE();
        __syncthreads();    // bound warp skew: protects TMEM/B slot reuse
    }

    g_assign[blockIdx.x * BP + tid] = bidx;   // row = tid

    __syncthreads();
    if (tid == 0) {
        MBARRIER_INVAL(mbA);
        MBARRIER_INVAL(mbCP);  MBARRIER_INVAL(mbCP + 8);
        MBARRIER_INVAL(mbMM);  MBARRIER_INVAL(mbMM + 8);
    }
    __syncthreads();
    if (wid == 0) {
        TCGEN05_RELINQUISH();
        TCGEN05_DEALLOC(tmem_base, 512);
    }
#else
    // ---------------- SIMT fp32 fallback (non-'a' compile pass) ----------------
    extern __shared__ char smem_raw[];
    float4* sE = (float4*)smem_raw;
    float4* sC = sE + BP * 32;

    const int t   = threadIdx.x;
    const int tx  = t & 15;
    const int ty8 = t >> 4;
    const int p0  = blockIdx.x * BP;
    const float4* cent4 = (const float4*)g_cent;

    for (int it = 0; it < 32; it++) {
        int f = t + it * 128;
        int r = f >> 5, c = f & 31;
        sE[r * 32 + c] = emb[(size_t)(p0 + r) * D4 + c];
    }

    float best[16];
    int   bidx[16];
#pragma unroll
    for (int i = 0; i < 16; i++) { best[i] = -3.402823466e38f; bidx[i] = 0; }

    for (int ch = 0; ch < K / 64; ch++) {
        __syncthreads();
        for (int it = 0; it < 16; it++) {
            int f = t + it * 128;
            int r = f >> 5, c = f & 31;
            sC[r * 33 + c] = cent4[(size_t)(ch * 64 + r) * D4 + c];
        }
        __syncthreads();

        float acc[16][4];
#pragma unroll
        for (int i = 0; i < 16; i++)
#pragma unroll
            for (int j = 0; j < 4; j++) acc[i][j] = 0.0f;

#pragma unroll 2
        for (int d4 = 0; d4 < D4; d4++) {
            float4 c4[4];
#pragma unroll
            for (int j = 0; j < 4; j++) c4[j] = sC[(tx + 16 * j) * 33 + d4];
#pragma unroll
            for (int i = 0; i < 16; i++) {
                float4 e = sE[(ty8 + 8 * i) * 32 + d4];
#pragma unroll
                for (int j = 0; j < 4; j++) {
                    acc[i][j] += e.x * c4[j].x;
                    acc[i][j] += e.y * c4[j].y;
                    acc[i][j] += e.z * c4[j].z;
                    acc[i][j] += e.w * c4[j].w;
                }
            }
        }
#pragma unroll
        for (int j = 0; j < 4; j++) {
            int idx = ch * 64 + tx + 16 * j;
#pragma unroll
            for (int i = 0; i < 16; i++) {
                float v = acc[i][j];
                if (v > best[i] || (v == best[i] && idx < bidx[i])) {
                    best[i] = v; bidx[i] = idx;
                }
            }
        }
    }

#pragma unroll
    for (int off = 1; off < 16; off <<= 1) {
#pragma unroll
        for (int i = 0; i < 16; i++) {
            float ov = __shfl_xor_sync(0xffffffffu, best[i], off);
            int   oi = __shfl_xor_sync(0xffffffffu, bidx[i], off);
            if (ov > best[i] || (ov == best[i] && oi < bidx[i])) {
                best[i] = ov; bidx[i] = oi;
            }
        }
    }
    if (tx == 0) {
#pragma unroll
        for (int i = 0; i < 16; i++)
            g_assign[p0 + ty8 + 8 * i] = bidx[i];
    }
#endif
}

// ---------------------------------------------------------------------------
__global__ void accum_kernel(const float4* __restrict__ emb) {
    int gw   = (blockIdx.x * blockDim.x + threadIdx.x) >> 5;
    int lane = threadIdx.x & 31;
    if (gw >= N_PTS) return;
    float4 v = emb[(size_t)gw * D4 + lane];
    int a = g_assign[gw];
    float* dst = g_sums + (size_t)a * D + lane * 4;
    asm volatile("red.global.add.v4.f32 [%0], {%1,%2,%3,%4};"
                 :: "l"(dst), "f"(v.x), "f"(v.y), "f"(v.z), "f"(v.w)
                 : "memory");
    if (lane == 0) atomicAdd(&g_counts[a], 1.0f);
}

// ---------------------------------------------------------------------------
__global__ void update_kernel() {
    int k = blockIdx.x;
    int d = threadIdx.x;
    float cnt = g_counts[k];
    float s   = g_sums[(size_t)k * D + d];
    float old = g_cent[(size_t)k * D + d];
    float val = (cnt > 0.0f) ? (s / fmaxf(cnt, 1.0f)) : old;

    float sq = val * val;
#pragma unroll
    for (int off = 16; off > 0; off >>= 1)
        sq += __shfl_xor_sync(0xffffffffu, sq, off);

    __shared__ float wsum[4];
    int warp = d >> 5, lane = d & 31;
    if (lane == 0) wsum[warp] = sq;
    __syncthreads();
    float tot = wsum[0] + wsum[1] + wsum[2] + wsum[3];
    float nrm = fmaxf(sqrtf(tot), 1e-12f);

    g_cent[(size_t)k * D + d] = val / nrm;
    g_sums[(size_t)k * D + d] = 0.0f;
    if (d == 0) g_counts[k] = 0.0f;
}

// ---------------------------------------------------------------------------
__global__ void out_concat_f32(float* __restrict__ out) {
    int i = blockIdx.x * blockDim.x + threadIdx.x;
    if (i < N_PTS) out[i] = (float)g_assign[i];
    if (i < K * D) out[N_PTS + i] = g_cent[i];
}
__global__ void out_assign_i32(int* __restrict__ out) {
    int i = blockIdx.x * blockDim.x + threadIdx.x;
    if (i < N_PTS) out[i] = g_assign[i];
}
__global__ void out_cent_f32(float* __restrict__ out) {
    int i = blockIdx.x * blockDim.x + threadIdx.x;
    if (i < K * D) out[i] = g_cent[i];
}

// ---------------------------------------------------------------------------
extern "C" void kernel_launch(void* const* d_in, const int* in_sizes, int n_in,
                              void* d_out, int out_size) {
    const float* emb   = (const float*)d_in[0];
    const float* initc = (const float*)d_in[1];
    if (n_in >= 2 && in_sizes[0] == K * D && in_sizes[1] == N_PTS * D) {
        const float* tmp = emb; emb = initc; initc = tmp;
    }

    cudaFuncSetAttribute(assign_tc_kernel,
                         cudaFuncAttributeMaxDynamicSharedMemorySize, SMEM_DYN_BYTES);

    init_kernel<<<(K * D + 255) / 256, 256>>>(initc);
    emb_split_kernel<<<NTILE, 256>>>((const float4*)emb);

    for (int it = 0; it < NITER; it++) {
        cent_split_kernel<<<64, 256>>>();
        assign_tc_kernel<<<N_PTS / BP, 128, SMEM_DYN_BYTES>>>((const float4*)emb);
        accum_kernel<<<(N_PTS * 32) / 256, 256>>>((const float4*)emb);
        update_kernel<<<K, D>>>();
    }

    if (out_size == N_PTS) {
        out_assign_i32<<<N_PTS / 256, 256>>>((int*)d_out);
    } else if (out_size == K * D) {
        out_cent_f32<<<(K * D) / 256, 256>>>((float*)d_out);
    } else {
        out_concat_f32<<<(N_PTS + 255) / 256, 256>>>((float*)d_out);
    }
}

// round 9
// speedup vs baseline: 2.2959x; 1.1111x over previous
#include <cuda_runtime.h>
#include <cuda_bf16.h>
#include <cstdint>

// Problem constants
#define N_PTS 262144
#define D     128
#define D4    32
#define K     512
#define NITER 5
#define NTILE (N_PTS / 128)

// E-step tiling
#define BP        128
#define NCHUNK    64
#define NCHUNKS   8
#define KSUB      2

// SMEM layout
#define A_SPLIT_BYTES  32768
#define A_TOTAL        (3 * A_SPLIT_BYTES)            // 98304
#define B_SPLIT_BYTES  16384
#define B_SLOT_BYTES   (3 * B_SPLIT_BYTES)            // 49152
#define B_TOTAL        (2 * B_SLOT_BYTES)             // 98304
#define SMEM_DYN_BYTES (1024 + A_TOTAL + B_TOTAL)     // 197632

#define A_TILE_U32  24576   // per-tile prepacked A image (98304 B)
#define B_IMG_U32   98304   // prepacked B image (393216 B)

// bf16 MMA idesc: dtype=F32, a=BF16, b=BF16, N=64, M=128
#define MMA_IDESC 0x08100490u
#define SMEM_DESC_BASE 0x4000404000010000ULL
#define SW128(o) ((o) ^ ((((unsigned)(o)) >> 3) & 0x70u))

#if defined(__CUDA_ARCH__) && (defined(__CUDA_ARCH_FEAT_SM103_ALL) || \
                               defined(__CUDA_ARCH_FEAT_SM100_ALL) || \
                               defined(__CUDA_ARCH_FEAT_SM101_ALL))
#define HAVE_TCGEN05 1
#else
#define HAVE_TCGEN05 0
#endif

// Scratch state
__device__ float    g_cent[K * D];
__device__ float    g_sums[K * D];
__device__ float    g_counts[K];
__device__ int      g_assign[N_PTS];
__device__ __align__(128) unsigned g_embA[NTILE * A_TILE_U32];
__device__ __align__(128) unsigned g_centB[B_IMG_U32];

// ---------------------------------------------------------------------------
// PTX helpers
// ---------------------------------------------------------------------------
__device__ __forceinline__ unsigned smem_u32(const void* p) {
    unsigned a;
    asm("{ .reg .u64 t; cvta.to.shared.u64 t, %1; cvt.u32.u64 %0, t; }"
        : "=r"(a) : "l"(p));
    return a;
}

#define MBARRIER_INIT(a, c) \
    asm volatile("mbarrier.init.shared.b64 [%0], %1;" :: "r"(a), "r"(c) : "memory")
#define MBARRIER_INVAL(a) \
    asm volatile("mbarrier.inval.shared.b64 [%0];" :: "r"(a) : "memory")
#define MBARRIER_EXPECT_TX(a, b) \
    asm volatile("mbarrier.arrive.expect_tx.shared.b64 _, [%0], %1;" \
                 :: "r"(a), "r"(b) : "memory")

#define MBARRIER_WAIT_PARITY(mbar, parity) do { \
    unsigned _m = (mbar), _p = (parity), _d; \
    asm volatile("{\n\t.reg .pred p;\n\t" \
        "mbarrier.try_wait.parity.acquire.cta.shared::cta.b64 p, [%1], %2;\n\t" \
        "selp.b32 %0, 1, 0, p;\n\t}" : "=r"(_d) : "r"(_m), "r"(_p) : "memory"); \
    if (!_d) { \
        asm volatile("{\n\t.reg .pred P1;\n\t" \
            "WL_%=:\n\t" \
            "mbarrier.try_wait.parity.acquire.cta.shared::cta.b64 P1, [%0], %1, 0x989680;\n\t" \
            "@P1 bra.uni WD_%=;\n\tbra.uni WL_%=;\n\tWD_%=:\n\t}" \
            :: "r"(_m), "r"(_p) : "memory"); \
    } \
} while (0)

#define BULK_G2S(dst, src, bytes, mbar) \
    asm volatile("cp.async.bulk.shared::cta.global.mbarrier::complete_tx::bytes " \
                 "[%0], [%1], %2, [%3];" \
                 :: "r"(dst), "l"(src), "r"(bytes), "r"(mbar) : "memory")

#if HAVE_TCGEN05
#define TCGEN05_ALLOC(sa, n) \
    asm volatile("tcgen05.alloc.cta_group::1.sync.aligned.shared::cta.b32 [%0], %1;" \
                 :: "r"(sa), "r"(n) : "memory")
#define TCGEN05_DEALLOC(t, n) \
    asm volatile("tcgen05.dealloc.cta_group::1.sync.aligned.b32 %0, %1;" :: "r"(t), "r"(n))
#define TCGEN05_RELINQUISH() \
    asm volatile("tcgen05.relinquish_alloc_permit.cta_group::1.sync.aligned;")
#define TCGEN05_COMMIT(m) \
    asm volatile("tcgen05.commit.cta_group::1.mbarrier::arrive::one.shared::cluster.b64 [%0];" \
                 :: "r"(m) : "memory")
#define TCGEN05_FENCE_BEFORE() asm volatile("tcgen05.fence::before_thread_sync;" ::: "memory")
#define TCGEN05_FENCE_AFTER()  asm volatile("tcgen05.fence::after_thread_sync;"  ::: "memory")
#define TCGEN05_WAIT_LD()      asm volatile("tcgen05.wait::ld.sync.aligned;" ::: "memory")

#define TCGEN05_LD_32X32B_X32(r, tmem_addr) \
    asm volatile( \
        "tcgen05.ld.sync.aligned.32x32b.x32.b32 " \
        "{%0, %1, %2, %3, %4, %5, %6, %7, " \
        " %8, %9, %10, %11, %12, %13, %14, %15, " \
        " %16, %17, %18, %19, %20, %21, %22, %23, " \
        " %24, %25, %26, %27, %28, %29, %30, %31}, [%32];" \
        : "=r"((r)[0]),  "=r"((r)[1]),  "=r"((r)[2]),  "=r"((r)[3]), \
          "=r"((r)[4]),  "=r"((r)[5]),  "=r"((r)[6]),  "=r"((r)[7]), \
          "=r"((r)[8]),  "=r"((r)[9]),  "=r"((r)[10]), "=r"((r)[11]), \
          "=r"((r)[12]), "=r"((r)[13]), "=r"((r)[14]), "=r"((r)[15]), \
          "=r"((r)[16]), "=r"((r)[17]), "=r"((r)[18]), "=r"((r)[19]), \
          "=r"((r)[20]), "=r"((r)[21]), "=r"((r)[22]), "=r"((r)[23]), \
          "=r"((r)[24]), "=r"((r)[25]), "=r"((r)[26]), "=r"((r)[27]), \
          "=r"((r)[28]), "=r"((r)[29]), "=r"((r)[30]), "=r"((r)[31]) \
        : "r"(tmem_addr))

__device__ __forceinline__ void mma_bf16_ss(unsigned d_tmem, unsigned long long a_desc,
                                            unsigned long long b_desc, unsigned en) {
    asm volatile(
        "{\n\t.reg .pred p;\n\tsetp.ne.u32 p, %4, 0;\n\t"
        "tcgen05.mma.cta_group::1.kind::f16 [%0], %1, %2, %3, {%5, %5, %5, %5}, p;\n\t}"
        :: "r"(d_tmem), "l"(a_desc), "l"(b_desc), "r"(MMA_IDESC), "r"(en), "r"(0u)
        : "memory");
}
#endif  // HAVE_TCGEN05

__device__ __forceinline__ unsigned long long mk_desc(unsigned byte_addr) {
    return SMEM_DESC_BASE | (unsigned long long)((byte_addr >> 4) & 0x3FFFu);
}

__device__ __forceinline__ void split3_pack(float x, float y,
                                            unsigned& ph, unsigned& pl, unsigned& pr) {
    __nv_bfloat16 xh = __float2bfloat16_rn(x);
    float xr1 = x - __bfloat162float(xh);
    __nv_bfloat16 xl = __float2bfloat16_rn(xr1);
    __nv_bfloat16 xr = __float2bfloat16_rn(xr1 - __bfloat162float(xl));
    __nv_bfloat16 yh = __float2bfloat16_rn(y);
    float yr1 = y - __bfloat162float(yh);
    __nv_bfloat16 yl = __float2bfloat16_rn(yr1);
    __nv_bfloat16 yr = __float2bfloat16_rn(yr1 - __bfloat162float(yl));
    ph = (unsigned)__bfloat16_as_ushort(xh) | ((unsigned)__bfloat16_as_ushort(yh) << 16);
    pl = (unsigned)__bfloat16_as_ushort(xl) | ((unsigned)__bfloat16_as_ushort(yl) << 16);
    pr = (unsigned)__bfloat16_as_ushort(xr) | ((unsigned)__bfloat16_as_ushort(yr) << 16);
}

// ---------------------------------------------------------------------------
__global__ void init_kernel(const float* __restrict__ initc) {
    int i = blockIdx.x * blockDim.x + threadIdx.x;
    if (i < K * D) { g_cent[i] = initc[i]; g_sums[i] = 0.0f; }
    if (i < K)     g_counts[i] = 0.0f;
}

// ---------------------------------------------------------------------------
// Once per launch: pack embedding bf16 splits into swizzled tile images.
// ---------------------------------------------------------------------------
__global__ void emb_split_kernel(const float4* __restrict__ emb) {
    const int tile = blockIdx.x;
    const int w    = threadIdx.x >> 5;
    const int lane = threadIdx.x & 31;
    unsigned* out = g_embA + (size_t)tile * A_TILE_U32;
    const unsigned subbase = (unsigned)(lane >> 4) * 4096u;
    for (int r = w; r < 128; r += 8) {
        float4 v = emb[(size_t)(tile * 128 + r) * D4 + lane];
        unsigned off = (unsigned)(r * 128 + 8 * (lane & 15));
        unsigned s0 = SW128(off) >> 2, s1 = SW128(off + 4) >> 2;
        unsigned ph, pl, pr, qh, ql, qr;
        split3_pack(v.x, v.y, ph, pl, pr);
        split3_pack(v.z, v.w, qh, ql, qr);
        out[subbase + s0]          = ph;  out[subbase + s1]          = qh;
        out[8192u + subbase + s0]  = pl;  out[8192u + subbase + s1]  = ql;
        out[16384u + subbase + s0] = pr;  out[16384u + subbase + s1] = qr;
    }
}

// ---------------------------------------------------------------------------
// Once per iteration: pack centroid splits into swizzled image.
// ---------------------------------------------------------------------------
__global__ void cent_split_kernel() {
    const int gw   = (blockIdx.x * blockDim.x + threadIdx.x) >> 5;
    const int lane = threadIdx.x & 31;
    if (gw >= K) return;
    float4 v = ((const float4*)g_cent)[(size_t)gw * D4 + lane];
    const unsigned subbase = (unsigned)(lane >> 4) * 16384u;
    unsigned off = (unsigned)(gw * 128 + 8 * (lane & 15));
    unsigned s0 = SW128(off) >> 2, s1 = SW128(off + 4) >> 2;
    unsigned ph, pl, pr, qh, ql, qr;
    split3_pack(v.x, v.y, ph, pl, pr);
    split3_pack(v.z, v.w, qh, ql, qr);
    g_centB[subbase + s0]           = ph;  g_centB[subbase + s1]           = qh;
    g_centB[32768u + subbase + s0]  = pl;  g_centB[32768u + subbase + s1]  = ql;
    g_centB[65536u + subbase + s0]  = pr;  g_centB[65536u + subbase + s1]  = qr;
}

// ---------------------------------------------------------------------------
// E-step, sm_103a: tcgen05 pipeline. Single accumulator per chunk (smalls
// FIRST, then hh). All 8 chunks TMEM-resident; ONE deferred epilogue.
// Producer ring barriers (mbMM) are tid0-PRIVATE (B-slot reuse pacing; tid0
// observes every phase in order -> no aliasing). Consumers wait a single
// dedicated mbDONE commit issued after ALL MMAs (tcgen05.commit tracks all
// prior MMAs from this CTA) -> single phase, no aliasing possible.
// ---------------------------------------------------------------------------
__global__ void __launch_bounds__(128, 1)
assign_tc_kernel(const float4* __restrict__ emb) {
#if HAVE_TCGEN05
    extern __shared__ char smem[];
    const unsigned smem_base = smem_u32(smem);
    const unsigned tiles = (smem_base + 1024u + 1023u) & ~1023u;
    const unsigned a_base = tiles;
    const unsigned b_base = tiles + A_TOTAL;
    const unsigned mbA    = smem_base + 8;
    const unsigned mbCP   = smem_base + 16;   // +16, +24
    const unsigned mbMM   = smem_base + 32;   // +32, +40 (tid0-private)
    const unsigned mbDONE = smem_base + 48;

    const int tid = threadIdx.x;
    const int wid = tid >> 5;

    if (tid == 0) {
        MBARRIER_INIT(mbA, 1);
        MBARRIER_INIT(mbCP, 1);     MBARRIER_INIT(mbCP + 8, 1);
        MBARRIER_INIT(mbMM, 1);     MBARRIER_INIT(mbMM + 8, 1);
        MBARRIER_INIT(mbDONE, 1);
    }
    if (wid == 0) TCGEN05_ALLOC(smem_base, 512);
    __syncthreads();
    unsigned tmem_base;
    asm volatile("ld.shared.b32 %0, [%1];" : "=r"(tmem_base) : "r"(smem_base));

    auto issue_copyB = [&](int c) {
        const unsigned mb = mbCP + 8u * (unsigned)(c & 1);
        const unsigned dslot = b_base + (unsigned)((c & 1) * B_SLOT_BYTES);
        MBARRIER_EXPECT_TX(mb, 49152u);
#pragma unroll
        for (int s = 0; s < 3; s++) {
#pragma unroll
            for (int h = 0; h < 2; h++) {
                const unsigned* src = g_centB + (size_t)s * 32768 + (size_t)h * 16384
                                      + (size_t)c * 2048;
                unsigned dst = dslot + (unsigned)(s * B_SPLIT_BYTES + h * 8192);
                BULK_G2S(dst, src, 8192u, mb);
            }
        }
    };

    // Single accumulator at tmem + 64*c. Smalls first, then hh on top.
    auto issue_chunk = [&](int c) {
        const int PA[5] = {0, 1, 1, 0, 2};   // (h,l)(l,h)(l,l)(h,r)(r,h)
        const int PB[5] = {1, 0, 1, 2, 0};
        const unsigned d_t = tmem_base + (unsigned)(64 * c);
        const unsigned bslot = b_base + (unsigned)((c & 1) * B_SLOT_BYTES);
        unsigned en = 0;
#pragma unroll
        for (int sub = 0; sub < KSUB; sub++) {
#pragma unroll
            for (int ks = 0; ks < 4; ks++) {
                const unsigned ko  = (unsigned)(sub * 16384 + ks * 32);
                const unsigned kob = (unsigned)(sub * 8192 + ks * 32);
#pragma unroll
                for (int p = 0; p < 5; p++) {
                    mma_bf16_ss(d_t,
                                mk_desc(a_base + PA[p] * A_SPLIT_BYTES + ko),
                                mk_desc(bslot + PB[p] * B_SPLIT_BYTES + kob),
                                en);
                    en = 1;
                }
            }
        }
#pragma unroll
        for (int sub = 0; sub < KSUB; sub++) {
#pragma unroll
            for (int ks = 0; ks < 4; ks++) {
                const unsigned ko  = (unsigned)(sub * 16384 + ks * 32);
                const unsigned kob = (unsigned)(sub * 8192 + ks * 32);
                mma_bf16_ss(d_t, mk_desc(a_base + ko), mk_desc(bslot + kob), 1);
            }
        }
        TCGEN05_COMMIT(mbMM + 8u * (unsigned)(c & 1));
    };

    // ---- tid0 drives the whole pipeline ----
    if (tid == 0) {
        MBARRIER_EXPECT_TX(mbA, 98304u);
        BULK_G2S(a_base, g_embA + (size_t)blockIdx.x * A_TILE_U32, 98304u, mbA);
        issue_copyB(0);
        issue_copyB(1);
        MBARRIER_WAIT_PARITY(mbA, 0);
        for (int c = 0; c < NCHUNKS; c++) {
            if (c >= 2) {
                // B slot (c&1) reusable once chunk c-2's MMAs completed.
                // tid0 is sole waiter; observes each phase in order.
                MBARRIER_WAIT_PARITY(mbMM + 8u * (unsigned)(c & 1),
                                     ((c - 2) >> 1) & 1);
                issue_copyB(c);
            }
            MBARRIER_WAIT_PARITY(mbCP + 8u * (unsigned)(c & 1), (c >> 1) & 1);
            issue_chunk(c);
        }
        // Tracks ALL previously issued MMAs -> single consumer barrier.
        TCGEN05_COMMIT(mbDONE);
    }

    // ---- All threads: one wait, then deferred epilogue ----
    MBARRIER_WAIT_PARITY(mbDONE, 0);
    TCGEN05_FENCE_AFTER();

    float best = -3.402823466e38f;
    int   bidx = 0;
    unsigned rg[32];
#pragma unroll
    for (int q = 0; q < 16; q++) {
        TCGEN05_LD_32X32B_X32(rg, tmem_base + (unsigned)(32 * q));
        TCGEN05_WAIT_LD();
#pragma unroll
        for (int j = 0; j < 32; j++) {
            float v = __uint_as_float(rg[j]);
            int idx = 32 * q + j;
            if (v > best) { best = v; bidx = idx; }
        }
    }
    TCGEN05_FENCE_BEFORE();

    g_assign[blockIdx.x * BP + tid] = bidx;

    __syncthreads();
    if (tid == 0) {
        MBARRIER_INVAL(mbA);
        MBARRIER_INVAL(mbCP);  MBARRIER_INVAL(mbCP + 8);
        MBARRIER_INVAL(mbMM);  MBARRIER_INVAL(mbMM + 8);
        MBARRIER_INVAL(mbDONE);
    }
    __syncthreads();
    if (wid == 0) {
        TCGEN05_RELINQUISH();
        TCGEN05_DEALLOC(tmem_base, 512);
    }
#else
    // ---------------- SIMT fp32 fallback (non-'a' compile pass) ----------------
    extern __shared__ char smem_raw[];
    float4* sE = (float4*)smem_raw;
    float4* sC = sE + BP * 32;

    const int t   = threadIdx.x;
    const int tx  = t & 15;
    const int ty8 = t >> 4;
    const int p0  = blockIdx.x * BP;
    const float4* cent4 = (const float4*)g_cent;

    for (int it = 0; it < 32; it++) {
        int f = t + it * 128;
        int r = f >> 5, c = f & 31;
        sE[r * 32 + c] = emb[(size_t)(p0 + r) * D4 + c];
    }

    float best[16];
    int   bidx[16];
#pragma unroll
    for (int i = 0; i < 16; i++) { best[i] = -3.402823466e38f; bidx[i] = 0; }

    for (int ch = 0; ch < K / 64; ch++) {
        __syncthreads();
        for (int it = 0; it < 16; it++) {
            int f = t + it * 128;
            int r = f >> 5, c = f & 31;
            sC[r * 33 + c] = cent4[(size_t)(ch * 64 + r) * D4 + c];
        }
        __syncthreads();

        float acc[16][4];
#pragma unroll
        for (int i = 0; i < 16; i++)
#pragma unroll
            for (int j = 0; j < 4; j++) acc[i][j] = 0.0f;

#pragma unroll 2
        for (int d4 = 0; d4 < D4; d4++) {
            float4 c4[4];
#pragma unroll
            for (int j = 0; j < 4; j++) c4[j] = sC[(tx + 16 * j) * 33 + d4];
#pragma unroll
            for (int i = 0; i < 16; i++) {
                float4 e = sE[(ty8 + 8 * i) * 32 + d4];
#pragma unroll
                for (int j = 0; j < 4; j++) {
                    acc[i][j] += e.x * c4[j].x;
                    acc[i][j] += e.y * c4[j].y;
                    acc[i][j] += e.z * c4[j].z;
                    acc[i][j] += e.w * c4[j].w;
                }
            }
        }
#pragma unroll
        for (int j = 0; j < 4; j++) {
            int idx = ch * 64 + tx + 16 * j;
#pragma unroll
            for (int i = 0; i < 16; i++) {
                float v = acc[i][j];
                if (v > best[i] || (v == best[i] && idx < bidx[i])) {
                    best[i] = v; bidx[i] = idx;
                }
            }
        }
    }

#pragma unroll
    for (int off = 1; off < 16; off <<= 1) {
#pragma unroll
        for (int i = 0; i < 16; i++) {
            float ov = __shfl_xor_sync(0xffffffffu, best[i], off);
            int   oi = __shfl_xor_sync(0xffffffffu, bidx[i], off);
            if (ov > best[i] || (ov == best[i] && oi < bidx[i])) {
                best[i] = ov; bidx[i] = oi;
            }
        }
    }
    if (tx == 0) {
#pragma unroll
        for (int i = 0; i < 16; i++)
            g_assign[p0 + ty8 + 8 * i] = bidx[i];
    }
#endif
}

// ---------------------------------------------------------------------------
__global__ void accum_kernel(const float4* __restrict__ emb) {
    int gw   = (blockIdx.x * blockDim.x + threadIdx.x) >> 5;
    int lane = threadIdx.x & 31;
    if (gw >= N_PTS) return;
    float4 v = emb[(size_t)gw * D4 + lane];
    int a = g_assign[gw];
    float* dst = g_sums + (size_t)a * D + lane * 4;
    asm volatile("red.global.add.v4.f32 [%0], {%1,%2,%3,%4};"
                 :: "l"(dst), "f"(v.x), "f"(v.y), "f"(v.z), "f"(v.w)
                 : "memory");
    if (lane == 0) atomicAdd(&g_counts[a], 1.0f);
}

// ---------------------------------------------------------------------------
__global__ void update_kernel() {
    int k = blockIdx.x;
    int d = threadIdx.x;
    float cnt = g_counts[k];
    float s   = g_sums[(size_t)k * D + d];
    float old = g_cent[(size_t)k * D + d];
    float val = (cnt > 0.0f) ? (s / fmaxf(cnt, 1.0f)) : old;

    float sq = val * val;
#pragma unroll
    for (int off = 16; off > 0; off >>= 1)
        sq += __shfl_xor_sync(0xffffffffu, sq, off);

    __shared__ float wsum[4];
    int warp = d >> 5, lane = d & 31;
    if (lane == 0) wsum[warp] = sq;
    __syncthreads();
    float tot = wsum[0] + wsum[1] + wsum[2] + wsum[3];
    float nrm = fmaxf(sqrtf(tot), 1e-12f);

    g_cent[(size_t)k * D + d] = val / nrm;
    g_sums[(size_t)k * D + d] = 0.0f;
    if (d == 0) g_counts[k] = 0.0f;
}

// ---------------------------------------------------------------------------
__global__ void out_concat_f32(float* __restrict__ out) {
    int i = blockIdx.x * blockDim.x + threadIdx.x;
    if (i < N_PTS) out[i] = (float)g_assign[i];
    if (i < K * D) out[N_PTS + i] = g_cent[i];
}
__global__ void out_assign_i32(int* __restrict__ out) {
    int i = blockIdx.x * blockDim.x + threadIdx.x;
    if (i < N_PTS) out[i] = g_assign[i];
}
__global__ void out_cent_f32(float* __restrict__ out) {
    int i = blockIdx.x * blockDim.x + threadIdx.x;
    if (i < K * D) out[i] = g_cent[i];
}

// ---------------------------------------------------------------------------
extern "C" void kernel_launch(void* const* d_in, const int* in_sizes, int n_in,
                              void* d_out, int out_size) {
    const float* emb   = (const float*)d_in[0];
    const float* initc = (const float*)d_in[1];
    if (n_in >= 2 && in_sizes[0] == K * D && in_sizes[1] == N_PTS * D) {
        const float* tmp = emb; emb = initc; initc = tmp;
    }

    cudaFuncSetAttribute(assign_tc_kernel,
                         cudaFuncAttributeMaxDynamicSharedMemorySize, SMEM_DYN_BYTES);

    init_kernel<<<(K * D + 255) / 256, 256>>>(initc);
    emb_split_kernel<<<NTILE, 256>>>((const float4*)emb);

    for (int it = 0; it < NITER; it++) {
        cent_split_kernel<<<64, 256>>>();
        assign_tc_kernel<<<N_PTS / BP, 128, SMEM_DYN_BYTES>>>((const float4*)emb);
        accum_kernel<<<(N_PTS * 32) / 256, 256>>>((const float4*)emb);
        update_kernel<<<K, D>>>();
    }

    if (out_size == N_PTS) {
        out_assign_i32<<<N_PTS / 256, 256>>>((int*)d_out);
    } else if (out_size == K * D) {
        out_cent_f32<<<(K * D) / 256, 256>>>((float*)d_out);
    } else {
        out_concat_f32<<<(N_PTS + 255) / 256, 256>>>((float*)d_out);
    }
}